// round 17
// baseline (speedup 1.0000x reference)
#include <cuda_runtime.h>
#include <cuda_bf16.h>
#include <cuda_fp16.h>
#include <cstdint>

#define Nn   50000
#define Ee   800000
#define F_IN 512
#define H1   256
#define H2   32
#define Cc   16

// ---------------- scratch (device globals; no allocations allowed) ----------
static __device__ __half g_h1h[(size_t)Nn * H1];   // x @ W1 (fp16)
static __device__ __half g_x2h[(size_t)Nn * H1];   // relu(agg1+b1) (fp16)
static __device__ __half g_h2h[(size_t)Nn * H2];   // x2 @ W2 (fp16)
static __device__ __half g_x3h[(size_t)Nn * H2];   // relu(agg2+b2) (fp16)
static __device__ __half g_h3h[(size_t)Nn * Cc];   // x3 @ W3 (fp16)
static __device__ float g_dinv[Nn];
static __device__ int   g_deg[Nn];
static __device__ int   g_incl[Nn];
static __device__ int   g_rowstart[Nn];
static __device__ int   g_fill[Nn];
static __device__ int   g_col[Ee];
static __device__ int   g_blocksums[64];
static __device__ int   g_is64;
// W1^T fp16: [256 n][512 k];  W2^T fp16: [32 n][256 k]
static __device__ __half g_B[(size_t)H1 * F_IN];
static __device__ __half g_B2[(size_t)H2 * H1];

// ---------------- helpers ----------------------------------------------------
__device__ __forceinline__ uint32_t smem_u32(const void* p) {
    uint32_t a;
    asm("{ .reg .u64 t; cvta.to.shared.u64 t, %1; cvt.u32.u64 %0, t; }" : "=r"(a) : "l"(p));
    return a;
}
__device__ __forceinline__ void ldm_x4(unsigned* r, uint32_t addr) {
    asm volatile("ldmatrix.sync.aligned.m8n8.x4.shared.b16 {%0,%1,%2,%3}, [%4];"
                 : "=r"(r[0]), "=r"(r[1]), "=r"(r[2]), "=r"(r[3]) : "r"(addr));
}
__device__ __forceinline__ void mma_f16(float* c, const unsigned* a, const unsigned* b) {
    asm volatile(
        "mma.sync.aligned.m16n8k16.row.col.f32.f16.f16.f32 "
        "{%0,%1,%2,%3},{%4,%5,%6,%7},{%8,%9},{%0,%1,%2,%3};"
        : "+f"(c[0]), "+f"(c[1]), "+f"(c[2]), "+f"(c[3])
        : "r"(a[0]), "r"(a[1]), "r"(a[2]), "r"(a[3]), "r"(b[0]), "r"(b[1]));
}
__device__ __forceinline__ void cpa16(uint32_t dst, const void* src) {
    asm volatile("cp.async.cg.shared.global [%0], [%1], 16;" :: "r"(dst), "l"(src));
}
#define CPA_COMMIT() asm volatile("cp.async.commit_group;" ::: "memory")
#define CPA_WAIT1()  asm volatile("cp.async.wait_group 1;" ::: "memory")

// fp16 row-slice fused accumulate: acc[0..7] += w * h8(u)
__device__ __forceinline__ void h8_fma(uint4 u, float w, float* acc) {
    const __half2* h = (const __half2*)&u;
#pragma unroll
    for (int i = 0; i < 4; i++) {
        float2 f = __half22float2(h[i]);
        acc[2 * i]     += w * f.x;
        acc[2 * i + 1] += w * f.y;
    }
}

// ---------------- edge-index dtype detection --------------------------------
__global__ void k_detect(const unsigned int* __restrict__ w) {
    if (threadIdx.x == 0 && blockIdx.x == 0) {
        int is64 = 1;
        for (int i = 1; i < 512; i += 2) {
            if (w[i] != 0u) { is64 = 0; break; }
        }
        g_is64 = is64;
    }
}
__device__ __forceinline__ int load_idx(const void* __restrict__ ei, long long idx) {
    if (g_is64) return (int)((const long long*)ei)[idx];
    return ((const int*)ei)[idx];
}

// ---------------- CSR build --------------------------------------------------
__global__ void k_zero_deg() {
    int i = blockIdx.x * blockDim.x + threadIdx.x;
    if (i < Nn) g_deg[i] = 0;
}
__global__ void k_count(const void* __restrict__ ei) {
    int e = blockIdx.x * blockDim.x + threadIdx.x;
    if (e < Ee) atomicAdd(&g_deg[load_idx(ei, (long long)Ee + e)], 1);
}
__global__ void k_scan1() {
    __shared__ int s[1024];
    int t = threadIdx.x;
    int i = blockIdx.x * 1024 + t;
    s[t] = (i < Nn) ? g_deg[i] : 0;
    __syncthreads();
    for (int off = 1; off < 1024; off <<= 1) {
        int add = (t >= off) ? s[t - off] : 0;
        __syncthreads();
        s[t] += add;
        __syncthreads();
    }
    if (i < Nn) g_incl[i] = s[t];
    if (t == 1023) g_blocksums[blockIdx.x] = s[1023];
}
__global__ void k_scan2(int nblocks) {
    if (threadIdx.x == 0) {
        int run = 0;
        for (int i = 0; i < nblocks; i++) { int v = g_blocksums[i]; g_blocksums[i] = run; run += v; }
    }
}
__global__ void k_scan3() {
    int i = blockIdx.x * blockDim.x + threadIdx.x;
    if (i < Nn) {
        int deg = g_deg[i];
        int start = g_incl[i] - deg + g_blocksums[i >> 10];
        g_rowstart[i] = start;
        g_fill[i] = start;
        g_dinv[i] = rsqrtf((float)(deg + 1));
    }
}
__global__ void k_scatter(const void* __restrict__ ei) {
    int e = blockIdx.x * blockDim.x + threadIdx.x;
    if (e < Ee) {
        int s = load_idx(ei, e);
        int d = load_idx(ei, (long long)Ee + e);
        int pos = atomicAdd(&g_fill[d], 1);
        g_col[pos] = s;
    }
}

// ---------------- W1^T + W2^T -> fp16 -----------------------------------------
__global__ void k_cvtW(const float* __restrict__ W1, const float* __restrict__ W2) {
    int i = blockIdx.x * blockDim.x + threadIdx.x;
    if (i < F_IN * H1) {
        int k = i >> 8;
        int n = i & 255;
        g_B[(size_t)n * F_IN + k] = __float2half_rn(W1[i]);
    } else if (i < F_IN * H1 + H1 * H2) {
        int j = i - F_IN * H1;
        int k = j >> 5;
        int n = j & 31;
        g_B2[(size_t)n * H1 + k] = __float2half_rn(W2[j]);
    }
}

// ---------------- GEMM1: fp16 mma.sync, split-N, 3 CTA/SM --------------------
// Block 64 rows x 128 cols (bid&1 selects col-half), 256 thr = 8 warps (2x4),
// warp 32x32. K chunks of 64, double-buffered. Stage (24KB): A[8K] B[16K].
#define ST_A  0
#define ST_B  8192
#define ST_SZ 24576
#define SM1_SZ (2 * ST_SZ)

struct APref { float4 v[2][2]; };

__device__ __forceinline__ void loadA_regs(const float* __restrict__ A, int row0,
                                           int k0, int tid, APref& ap) {
#pragma unroll
    for (int j = 0; j < 2; j++) {
        int i = tid + j * 256;          // 0..511 over 64 rows x 8 segs
        int r = i >> 3;
        int seg = i & 7;
        int gr = row0 + r;
        if (gr >= Nn) gr = Nn - 1;
        const float4* p = (const float4*)(A + (size_t)gr * F_IN + k0 + seg * 8);
        ap.v[j][0] = p[0];
        ap.v[j][1] = p[1];
    }
}
__device__ __forceinline__ void storeA_smem(char* sm, int boff, int tid, const APref& ap) {
#pragma unroll
    for (int j = 0; j < 2; j++) {
        int i = tid + j * 256;
        int r = i >> 3;
        int seg = i & 7;
        float4 v0 = ap.v[j][0], v1 = ap.v[j][1];
        uint4 h;
        __half2 h0 = __floats2half2_rn(v0.x, v0.y);
        __half2 h1 = __floats2half2_rn(v0.z, v0.w);
        __half2 h2 = __floats2half2_rn(v1.x, v1.y);
        __half2 h3 = __floats2half2_rn(v1.z, v1.w);
        h.x = *(unsigned*)&h0; h.y = *(unsigned*)&h1;
        h.z = *(unsigned*)&h2; h.w = *(unsigned*)&h3;
        int ps = seg ^ (r & 7);
        *(uint4*)(sm + boff + ST_A + (r * 8 + ps) * 16) = h;
    }
}
__device__ __forceinline__ void issueB_cpasync(uint32_t sbase, int boff, int col0,
                                               int k0, int tid) {
#pragma unroll
    for (int j = 0; j < 4; j++) {
        int i = tid + j * 256;          // 0..1023 over 128 n x 8 segs
        int n = i >> 3;
        int seg = i & 7;
        int ps = seg ^ (n & 7);
        size_t src = ((size_t)(col0 + n) * F_IN + k0 + seg * 8) * 2;
        uint32_t doff = (uint32_t)((n * 8 + ps) * 16);
        cpa16(sbase + boff + ST_B + doff, (const char*)g_B + src);
    }
}

__global__ void __launch_bounds__(256, 3) k_gemm1_mma(const float* __restrict__ A) {
    extern __shared__ char sm[];
    uint32_t sbase = smem_u32(sm);
    int tid = threadIdx.x;
    int wid = tid >> 5;
    int lane = tid & 31;
    int warp_m = wid & 1;           // 2 row slices of 32
    int warp_n = wid >> 1;          // 4 col slices of 32
    int row0 = (blockIdx.x >> 1) * 64;
    int col0 = (blockIdx.x & 1) * 128;

    float acc[2][4][4];
#pragma unroll
    for (int mt = 0; mt < 2; mt++)
#pragma unroll
        for (int nt = 0; nt < 4; nt++)
#pragma unroll
            for (int q = 0; q < 4; q++) acc[mt][nt][q] = 0.f;

    APref ap;
    loadA_regs(A, row0, 0, tid, ap);
    issueB_cpasync(sbase, 0, col0, 0, tid);
    CPA_COMMIT();
    storeA_smem(sm, 0, tid, ap);

#pragma unroll 1
    for (int ck = 0; ck < 8; ck++) {
        int cur = ck & 1;
        int boff_cur = cur * ST_SZ;
        int boff_nxt = (cur ^ 1) * ST_SZ;
        if (ck < 7) {
            loadA_regs(A, row0, (ck + 1) * 64, tid, ap);
            issueB_cpasync(sbase, boff_nxt, col0, (ck + 1) * 64, tid);
        }
        CPA_COMMIT();
        CPA_WAIT1();
        __syncthreads();

        uint32_t baseA = sbase + boff_cur + ST_A;
        uint32_t baseB = sbase + boff_cur + ST_B;
#pragma unroll
        for (int s = 0; s < 4; s++) {
            unsigned ah[2][4];
#pragma unroll
            for (int mt = 0; mt < 2; mt++) {
                int q = lane >> 3;
                int r = warp_m * 32 + mt * 16 + (q & 1) * 8 + (lane & 7);
                int seg = s * 2 + (q >> 1);
                uint32_t off = (uint32_t)(r * 8 + (seg ^ (r & 7))) * 16;
                ldm_x4(ah[mt], baseA + off);
            }
#pragma unroll
            for (int jp = 0; jp < 2; jp++) {
                unsigned b4[4];
                int q = lane >> 3;
                int n = warp_n * 32 + (jp * 2 + (q >> 1)) * 8 + (lane & 7);
                int seg = s * 2 + (q & 1);
                uint32_t off = (uint32_t)(n * 8 + (seg ^ (n & 7))) * 16;
                ldm_x4(b4, baseB + off);
                mma_f16(acc[0][jp * 2],     ah[0], &b4[0]);
                mma_f16(acc[1][jp * 2],     ah[1], &b4[0]);
                mma_f16(acc[0][jp * 2 + 1], ah[0], &b4[2]);
                mma_f16(acc[1][jp * 2 + 1], ah[1], &b4[2]);
            }
        }
        if (ck < 7) storeA_smem(sm, boff_nxt, tid, ap);
        __syncthreads();
    }

#pragma unroll
    for (int mt = 0; mt < 2; mt++)
#pragma unroll
        for (int nt = 0; nt < 4; nt++) {
            int r = row0 + warp_m * 32 + mt * 16 + (lane >> 2);
            int col = col0 + warp_n * 32 + nt * 8 + (lane & 3) * 2;
            if (r < Nn)
                *(__half2*)(g_h1h + (size_t)r * H1 + col) =
                    __floats2half2_rn(acc[mt][nt][0], acc[mt][nt][1]);
            if (r + 8 < Nn)
                *(__half2*)(g_h1h + (size_t)(r + 8) * H1 + col) =
                    __floats2half2_rn(acc[mt][nt][2], acc[mt][nt][3]);
        }
}

// ---------------- GEMM2: x2h [Nn,256] fp16 @ W2 -> h2h (tensor core) --------
#define ST2_A  0
#define ST2_B  16384
#define ST2_SZ 20480
#define SM2_SZ (2 * ST2_SZ)

__device__ __forceinline__ void g2_stageA(uint32_t sbase, int boff, int row0,
                                          int k0, int tid) {
#pragma unroll
    for (int j = 0; j < 8; j++) {
        int i = tid + j * 128;
        int r = i >> 3;
        int seg = i & 7;
        int gr = row0 + r;
        if (gr >= Nn) gr = Nn - 1;
        int ps = seg ^ (r & 7);
        size_t src = ((size_t)gr * H1 + k0 + seg * 8) * 2;
        cpa16(sbase + boff + ST2_A + (uint32_t)((r * 8 + ps) * 16), (const char*)g_x2h + src);
    }
}
__device__ __forceinline__ void g2_stageB(uint32_t sbase, int boff, int k0, int tid) {
#pragma unroll
    for (int j = 0; j < 2; j++) {
        int i = tid + j * 128;
        int n = i >> 3;
        int seg = i & 7;
        int ps = seg ^ (n & 7);
        size_t src = ((size_t)n * H1 + k0 + seg * 8) * 2;
        cpa16(sbase + boff + ST2_B + (uint32_t)((n * 8 + ps) * 16), (const char*)g_B2 + src);
    }
}

__global__ void __launch_bounds__(128) k_gemm2_mma() {
    extern __shared__ char sm[];
    uint32_t sbase = smem_u32(sm);
    int tid = threadIdx.x;
    int wid = tid >> 5;
    int lane = tid & 31;
    int row0 = blockIdx.x * 128;

    float acc[2][4][4];
#pragma unroll
    for (int mt = 0; mt < 2; mt++)
#pragma unroll
        for (int nt = 0; nt < 4; nt++)
#pragma unroll
            for (int q = 0; q < 4; q++) acc[mt][nt][q] = 0.f;

    g2_stageA(sbase, 0, row0, 0, tid);
    g2_stageB(sbase, 0, 0, tid);
    CPA_COMMIT();

#pragma unroll 1
    for (int ck = 0; ck < 4; ck++) {
        int cur = ck & 1;
        int boff_cur = cur * ST2_SZ;
        int boff_nxt = (cur ^ 1) * ST2_SZ;
        if (ck < 3) {
            g2_stageA(sbase, boff_nxt, row0, (ck + 1) * 64, tid);
            g2_stageB(sbase, boff_nxt, (ck + 1) * 64, tid);
        }
        CPA_COMMIT();
        CPA_WAIT1();
        __syncthreads();

        uint32_t baseA = sbase + boff_cur + ST2_A;
        uint32_t baseB = sbase + boff_cur + ST2_B;
#pragma unroll
        for (int s = 0; s < 4; s++) {
            unsigned ah[2][4];
#pragma unroll
            for (int mt = 0; mt < 2; mt++) {
                int q = lane >> 3;
                int r = wid * 32 + mt * 16 + (q & 1) * 8 + (lane & 7);
                int seg = s * 2 + (q >> 1);
                uint32_t off = (uint32_t)(r * 8 + (seg ^ (r & 7))) * 16;
                ldm_x4(ah[mt], baseA + off);
            }
#pragma unroll
            for (int jp = 0; jp < 2; jp++) {
                unsigned b4[4];
                int q = lane >> 3;
                int n = (jp * 2 + (q >> 1)) * 8 + (lane & 7);
                int seg = s * 2 + (q & 1);
                uint32_t off = (uint32_t)(n * 8 + (seg ^ (n & 7))) * 16;
                ldm_x4(b4, baseB + off);
                mma_f16(acc[0][jp * 2],     ah[0], &b4[0]);
                mma_f16(acc[1][jp * 2],     ah[1], &b4[0]);
                mma_f16(acc[0][jp * 2 + 1], ah[0], &b4[2]);
                mma_f16(acc[1][jp * 2 + 1], ah[1], &b4[2]);
            }
        }
        __syncthreads();
    }

#pragma unroll
    for (int mt = 0; mt < 2; mt++)
#pragma unroll
        for (int nt = 0; nt < 4; nt++) {
            int r = row0 + wid * 32 + mt * 16 + (lane >> 2);
            int col = nt * 8 + (lane & 3) * 2;
            if (r < Nn)
                *(__half2*)(g_h2h + (size_t)r * H2 + col) =
                    __floats2half2_rn(acc[mt][nt][0], acc[mt][nt][1]);
            if (r + 8 < Nn)
                *(__half2*)(g_h2h + (size_t)(r + 8) * H2 + col) =
                    __floats2half2_rn(acc[mt][nt][2], acc[mt][nt][3]);
        }
}

// ---------------- GEMM3: g_x3h [Nn,32] fp16 x W3 [32,16] -> g_h3h -----------
__global__ void k_gemm3(const float* __restrict__ W) {
    __shared__ float sW[32 * 16];
    int tid = threadIdx.x;
    for (int i = tid; i < 32 * 16; i += 256) sW[i] = W[i];
    __syncthreads();
    int row = blockIdx.x * 256 + tid;
    if (row >= Nn) return;
    float acc[16];
#pragma unroll
    for (int c = 0; c < 16; c++) acc[c] = 0.f;
    const uint4* ap = (const uint4*)(g_x3h + (size_t)row * H2);
#pragma unroll
    for (int q4 = 0; q4 < 4; q4++) {
        uint4 u = ap[q4];
        const __half2* h = (const __half2*)&u;
#pragma unroll
        for (int p = 0; p < 4; p++) {
            float2 f = __half22float2(h[p]);
            int k = q4 * 8 + p * 2;
#pragma unroll
            for (int c = 0; c < 16; c++) {
                acc[c] += f.x * sW[(k + 0) * 16 + c];
                acc[c] += f.y * sW[(k + 1) * 16 + c];
            }
        }
    }
    uint4 o0, o1;
    __half2 p0 = __floats2half2_rn(acc[0], acc[1]);
    __half2 p1 = __floats2half2_rn(acc[2], acc[3]);
    __half2 p2 = __floats2half2_rn(acc[4], acc[5]);
    __half2 p3 = __floats2half2_rn(acc[6], acc[7]);
    __half2 p4 = __floats2half2_rn(acc[8], acc[9]);
    __half2 p5 = __floats2half2_rn(acc[10], acc[11]);
    __half2 p6 = __floats2half2_rn(acc[12], acc[13]);
    __half2 p7 = __floats2half2_rn(acc[14], acc[15]);
    o0.x = *(unsigned*)&p0; o0.y = *(unsigned*)&p1;
    o0.z = *(unsigned*)&p2; o0.w = *(unsigned*)&p3;
    o1.x = *(unsigned*)&p4; o1.y = *(unsigned*)&p5;
    o1.z = *(unsigned*)&p6; o1.w = *(unsigned*)&p7;
    uint4* op = (uint4*)(g_h3h + (size_t)row * Cc);
    op[0] = o0;
    op[1] = o1;
}

// ---------------- Aggregation ------------------------------------------------
__global__ void k_agg256(const float* __restrict__ bias) {
    int warp = threadIdx.x >> 5;
    int lane = threadIdx.x & 31;
    int node = blockIdx.x * 8 + warp;
    if (node >= Nn) return;
    float wd = g_dinv[node];
    const uint4* hp = (const uint4*)(g_h1h);
    float acc[8] = {};
    h8_fma(hp[(size_t)node * 32 + lane], wd, acc);
    int beg = g_rowstart[node];
    int cnt = g_deg[node];
    int j = 0;
    for (; j + 2 <= cnt; j += 2) {
        int s0 = g_col[beg + j];
        int s1 = g_col[beg + j + 1];
        float w0 = g_dinv[s0];
        float w1 = g_dinv[s1];
        uint4 u = hp[(size_t)s0 * 32 + lane];
        uint4 v = hp[(size_t)s1 * 32 + lane];
        h8_fma(u, w0, acc);
        h8_fma(v, w1, acc);
    }
    if (j < cnt) {
        int s = g_col[beg + j];
        h8_fma(hp[(size_t)s * 32 + lane], g_dinv[s], acc);
    }
    const float4* bp = (const float4*)(bias + lane * 8);
    float4 b0 = bp[0], b1 = bp[1];
    float r0 = fmaxf(acc[0] * wd + b0.x, 0.f), r1 = fmaxf(acc[1] * wd + b0.y, 0.f);
    float r2 = fmaxf(acc[2] * wd + b0.z, 0.f), r3 = fmaxf(acc[3] * wd + b0.w, 0.f);
    float r4 = fmaxf(acc[4] * wd + b1.x, 0.f), r5 = fmaxf(acc[5] * wd + b1.y, 0.f);
    float r6 = fmaxf(acc[6] * wd + b1.z, 0.f), r7 = fmaxf(acc[7] * wd + b1.w, 0.f);
    uint4 o;
    __half2 o0 = __floats2half2_rn(r0, r1);
    __half2 o1 = __floats2half2_rn(r2, r3);
    __half2 o2 = __floats2half2_rn(r4, r5);
    __half2 o3 = __floats2half2_rn(r6, r7);
    o.x = *(unsigned*)&o0; o.y = *(unsigned*)&o1;
    o.z = *(unsigned*)&o2; o.w = *(unsigned*)&o3;
    *(uint4*)(g_x2h + (size_t)node * 256 + lane * 8) = o;
}

__global__ void k_agg32(const float* __restrict__ bias) {
    int warp = threadIdx.x >> 5;
    int lane = threadIdx.x & 31;
    int node = blockIdx.x * 8 + warp;
    if (node >= Nn) return;
    float wd = g_dinv[node];
    float acc = wd * __half2float(g_h2h[(size_t)node * 32 + lane]);
    int beg = g_rowstart[node];
    int cnt = g_deg[node];
    int j = 0;
    for (; j + 2 <= cnt; j += 2) {
        int s0 = g_col[beg + j];
        int s1 = g_col[beg + j + 1];
        float w0 = g_dinv[s0];
        float w1 = g_dinv[s1];
        float u = __half2float(g_h2h[(size_t)s0 * 32 + lane]);
        float v = __half2float(g_h2h[(size_t)s1 * 32 + lane]);
        acc += w0 * u + w1 * v;
    }
    if (j < cnt) {
        int s = g_col[beg + j];
        acc += g_dinv[s] * __half2float(g_h2h[(size_t)s * 32 + lane]);
    }
    float r = acc * wd + bias[lane];
    g_x3h[(size_t)node * 32 + lane] = __float2half_rn(fmaxf(r, 0.f));
}

__global__ void k_agg16(const float* __restrict__ bias, float* __restrict__ out) {
    int tid = threadIdx.x;
    int local = tid & 15;
    int node = blockIdx.x * 16 + (tid >> 4);
    if (node >= Nn) return;
    float wd = g_dinv[node];
    float acc = wd * __half2float(g_h3h[(size_t)node * 16 + local]);
    int beg = g_rowstart[node];
    int cnt = g_deg[node];
    int j = 0;
    for (; j + 2 <= cnt; j += 2) {
        int s0 = g_col[beg + j];
        int s1 = g_col[beg + j + 1];
        float u = __half2float(g_h3h[(size_t)s0 * 16 + local]);
        float v = __half2float(g_h3h[(size_t)s1 * 16 + local]);
        acc += g_dinv[s0] * u + g_dinv[s1] * v;
    }
    if (j < cnt) {
        int s = g_col[beg + j];
        acc += g_dinv[s] * __half2float(g_h3h[(size_t)s * 16 + local]);
    }
    out[(size_t)node * 16 + local] = acc * wd + bias[local];
}

// ---------------- stream/event singletons (created once, reused) -------------
static cudaStream_t get_side_stream() {
    static cudaStream_t s = [] {
        cudaStream_t t;
        cudaStreamCreateWithFlags(&t, cudaStreamNonBlocking);
        return t;
    }();
    return s;
}
static cudaEvent_t get_event(int which) {
    static cudaEvent_t e0 = [] {
        cudaEvent_t e;
        cudaEventCreateWithFlags(&e, cudaEventDisableTiming);
        return e;
    }();
    static cudaEvent_t e1 = [] {
        cudaEvent_t e;
        cudaEventCreateWithFlags(&e, cudaEventDisableTiming);
        return e;
    }();
    return which ? e1 : e0;
}

// ---------------- launch -----------------------------------------------------
extern "C" void kernel_launch(void* const* d_in, const int* in_sizes, int n_in,
                              void* d_out, int out_size) {
    const float* x   = (const float*)d_in[0];
    const void*  ei  = (const void*)d_in[1];
    const float* W1  = (const float*)d_in[2];
    const float* b1  = (const float*)d_in[3];
    const float* W2  = (const float*)d_in[4];
    const float* b2  = (const float*)d_in[5];
    const float* W3  = (const float*)d_in[6];
    const float* b3  = (const float*)d_in[7];
    float* out       = (float*)d_out;

    cudaFuncSetAttribute(k_gemm1_mma, cudaFuncAttributeMaxDynamicSharedMemorySize, SM1_SZ);
    cudaFuncSetAttribute(k_gemm2_mma, cudaFuncAttributeMaxDynamicSharedMemorySize, SM2_SZ);

    const int scanBlocks = (Nn + 1023) / 1024;   // 49
    cudaStream_t side = get_side_stream();
    cudaEvent_t evFork = get_event(0);
    cudaEvent_t evJoin = get_event(1);

    cudaEventRecord(evFork, 0);
    cudaStreamWaitEvent(side, evFork, 0);

    k_detect<<<1, 32, 0, side>>>((const unsigned int*)ei);
    k_zero_deg<<<(Nn + 255) / 256, 256, 0, side>>>();
    k_cvtW<<<(F_IN * H1 + H1 * H2 + 255) / 256, 256>>>(W1, W2);
    k_gemm1_mma<<<((Nn + 63) / 64) * 2, 256, SM1_SZ>>>(x);
    k_count<<<(Ee + 255) / 256, 256, 0, side>>>(ei);
    k_scan1<<<scanBlocks, 1024, 0, side>>>();
    k_scan2<<<1, 32, 0, side>>>(scanBlocks);
    k_scan3<<<(Nn + 255) / 256, 256, 0, side>>>();
    k_scatter<<<(Ee + 255) / 256, 256, 0, side>>>(ei);
    cudaEventRecord(evJoin, side);

    cudaStreamWaitEvent(0, evJoin, 0);

    k_agg256<<<(Nn + 7) / 8, 256>>>(b1);
    k_gemm2_mma<<<(Nn + 127) / 128, 128, SM2_SZ>>>();
    k_agg32<<<(Nn + 7) / 8, 256>>>(b2);
    k_gemm3<<<(Nn + 255) / 256, 256>>>(W3);
    k_agg16<<<(Nn + 15) / 16, 256>>>(b3, out);
}